// round 13
// baseline (speedup 1.0000x reference)
#include <cuda_runtime.h>
#include <cuda_bf16.h>
#include <cstdint>

#define B_ 4
#define C_ 512
#define T_ 2048
#define H_ 8
#define CH 64
#define NGROUPS 32

// Scratch (static device arrays: allocation-free per harness rules)
__device__ __nv_bfloat16 g_xn [B_ * C_ * T_];
__device__ __nv_bfloat16 g_qkv[3 * B_ * C_ * T_];
__device__ __nv_bfloat16 g_att[B_ * C_ * T_];
__device__ __nv_bfloat16 g_wq [3 * C_ * C_];
__device__ __nv_bfloat16 g_wp [C_ * C_];

// ---------------------------------------------------------------------------
// helpers
// ---------------------------------------------------------------------------
__device__ __forceinline__ void mma16(float* d, uint32_t a0, uint32_t a1,
                                      uint32_t a2, uint32_t a3,
                                      uint32_t b0, uint32_t b1) {
    asm volatile(
        "mma.sync.aligned.m16n8k16.row.col.f32.bf16.bf16.f32 "
        "{%0,%1,%2,%3}, {%4,%5,%6,%7}, {%8,%9}, {%0,%1,%2,%3};\n"
        : "+f"(d[0]), "+f"(d[1]), "+f"(d[2]), "+f"(d[3])
        : "r"(a0), "r"(a1), "r"(a2), "r"(a3), "r"(b0), "r"(b1));
}
__device__ __forceinline__ void ldsm4(uint32_t& r0, uint32_t& r1, uint32_t& r2,
                                      uint32_t& r3, uint32_t addr) {
    asm volatile("ldmatrix.sync.aligned.m8n8.x4.shared.b16 {%0,%1,%2,%3}, [%4];"
                 : "=r"(r0), "=r"(r1), "=r"(r2), "=r"(r3) : "r"(addr));
}
__device__ __forceinline__ void ldsm4t(uint32_t& r0, uint32_t& r1, uint32_t& r2,
                                       uint32_t& r3, uint32_t addr) {
    asm volatile("ldmatrix.sync.aligned.m8n8.x4.trans.shared.b16 {%0,%1,%2,%3}, [%4];"
                 : "=r"(r0), "=r"(r1), "=r"(r2), "=r"(r3) : "r"(addr));
}
__device__ __forceinline__ void cp16(uint32_t dst, const void* src) {
    asm volatile("cp.async.cg.shared.global [%0], [%1], 16;\n" :: "r"(dst), "l"(src));
}
#define CP_COMMIT() asm volatile("cp.async.commit_group;\n" ::)
#define CP_WAIT0()  asm volatile("cp.async.wait_group 0;\n" ::)
#define CP_WAIT1()  asm volatile("cp.async.wait_group 1;\n" ::)

__device__ __forceinline__ uint32_t pack_bf16(float a, float b) {
    __nv_bfloat162 h = __floats2bfloat162_rn(a, b);
    return *(uint32_t*)&h;
}
__device__ __forceinline__ float ex2(float x) {
    float r;
    asm("ex2.approx.f32 %0, %1;" : "=f"(r) : "f"(x));
    return r;
}

// ---------------------------------------------------------------------------
// weights fp32 -> bf16 (both weight matrices in one launch)
// ---------------------------------------------------------------------------
__global__ __launch_bounds__(256) void cvt2_kernel(
    const float* __restrict__ s1, __nv_bfloat16* __restrict__ d1, int n1,
    const float* __restrict__ s2, __nv_bfloat16* __restrict__ d2, int n2) {
    const int i = blockIdx.x * 256 + threadIdx.x;
    const float* src; __nv_bfloat16* dst; int j;
    if (i < n1) { src = s1; dst = d1; j = i; }
    else if (i < n1 + n2) { src = s2; dst = d2; j = i - n1; }
    else return;
    float4 v = ((const float4*)src)[j];
    ((__nv_bfloat162*)dst)[2 * j]     = __floats2bfloat162_rn(v.x, v.y);
    ((__nv_bfloat162*)dst)[2 * j + 1] = __floats2bfloat162_rn(v.z, v.w);
}

// ---------------------------------------------------------------------------
// GroupNorm (fp32 in, bf16 out), 1024 threads
// ---------------------------------------------------------------------------
__global__ __launch_bounds__(1024) void gn_kernel(const float* __restrict__ x,
                                                  const float* __restrict__ w,
                                                  const float* __restrict__ bb,
                                                  __nv_bfloat16* __restrict__ out) {
    const int blk = blockIdx.x;
    const int g = blk & (NGROUPS - 1);
    const size_t base = (size_t)blk * (16 * T_);
    const float* xp = x + base;
    __nv_bfloat162* op = (__nv_bfloat162*)(out + base);
    const int tid = threadIdx.x;

    float s = 0.f, sq = 0.f;
    #pragma unroll
    for (int u = 0; u < 8; u++) {
        float4 v = ((const float4*)xp)[u * 1024 + tid];
        s  += v.x + v.y + v.z + v.w;
        sq += v.x * v.x + v.y * v.y + v.z * v.z + v.w * v.w;
    }
    #pragma unroll
    for (int o = 16; o; o >>= 1) {
        s  += __shfl_xor_sync(0xffffffffu, s,  o);
        sq += __shfl_xor_sync(0xffffffffu, sq, o);
    }
    __shared__ float rs[32], rq[32];
    __shared__ float mean_s, inv_s;
    const int warp = tid >> 5, lane = tid & 31;
    if (lane == 0) { rs[warp] = s; rq[warp] = sq; }
    __syncthreads();
    if (tid == 0) {
        float ts = 0.f, tq = 0.f;
        #pragma unroll
        for (int i = 0; i < 32; i++) { ts += rs[i]; tq += rq[i]; }
        const float inv_n = 1.0f / (16.0f * T_);
        float mean = ts * inv_n;
        float var = tq * inv_n - mean * mean;
        mean_s = mean;
        inv_s = rsqrtf(var + 1e-5f);
    }
    __syncthreads();
    const float mean = mean_s, inv = inv_s;
    #pragma unroll
    for (int u = 0; u < 8; u++) {
        const int i = u * 1024 + tid;
        const int c = (g << 4) + (i >> 9);
        const float wc = w[c], bc = bb[c];
        float4 v = ((const float4*)xp)[i];
        v.x = (v.x - mean) * inv * wc + bc;
        v.y = (v.y - mean) * inv * wc + bc;
        v.z = (v.z - mean) * inv * wc + bc;
        v.w = (v.w - mean) * inv * wc + bc;
        op[2 * i]     = __floats2bfloat162_rn(v.x, v.y);
        op[2 * i + 1] = __floats2bfloat162_rn(v.z, v.w);
    }
}

// ---------------------------------------------------------------------------
// bf16 tensor-core GEMM: block 128x128, k-tile 64 (dynamic smem, double buf),
// one sync per 64-K. 8 warps (4m x 2n), warp 32x64.
// mode 0: bf16 out w/ q,k scaling; mode 1: fp32 + resid.
// ---------------------------------------------------------------------------
#define GA_LD 36
#define GB_LD 68
#define GA_ST (128 * GA_LD)     // 4608 u32
#define GB_ST (64 * GB_LD)      // 4352 u32
#define GEMM_SMEM_BYTES ((2 * GA_ST + 2 * GB_ST) * 4)   // 71680

__global__ __launch_bounds__(256, 2) void gemm_kernel(
    const __nv_bfloat16* __restrict__ W, const __nv_bfloat16* __restrict__ X,
    const float* __restrict__ bias, const float* __restrict__ resid,
    void* __restrict__ Yv, int M, int mode) {
    const int N = T_, K = C_;
    extern __shared__ uint32_t smg[];
    const uint32_t sAb = (uint32_t)__cvta_generic_to_shared(smg);
    const uint32_t sBb = sAb + 2 * GA_ST * 4;

    const int n0 = blockIdx.x * 128, m0 = blockIdx.y * 128, b = blockIdx.z;
    const __nv_bfloat16* Xb = X + (size_t)b * K * N;
    const int tid = threadIdx.x;
    const int w = tid >> 5, lane = tid & 31;
    const int g = lane >> 2, tig = lane & 3;
    const int m0w = (w & 3) * 32, n0w = (w >> 2) * 64;

    auto issue = [&](int kt, int st) {
        const int k0 = kt * 64;
        #pragma unroll
        for (int u = 0; u < 4; u++) {        // A: 128 rows x 64 bf16
            const int id = u * 256 + tid, r = id >> 3, ch = id & 7;
            cp16(sAb + (st * GA_ST + r * GA_LD + ch * 4) * 4,
                 &W[(size_t)(m0 + r) * K + k0 + ch * 8]);
        }
        #pragma unroll
        for (int u = 0; u < 4; u++) {        // B: 64 rows x 128 bf16
            const int id = u * 256 + tid, r = id >> 4, ch = id & 15;
            cp16(sBb + (st * GB_ST + r * GB_LD + ch * 4) * 4,
                 &Xb[(size_t)(k0 + r) * N + n0 + ch * 8]);
        }
        CP_COMMIT();
    };

    float acc[2][8][4] = {};
    issue(0, 0);
    const int NT = K / 64;                    // 8
    for (int kt = 0; kt < NT; kt++) {
        CP_WAIT0();
        __syncthreads();
        if (kt + 1 < NT) issue(kt + 1, (kt + 1) & 1);
        const uint32_t sa = sAb + ((kt & 1) * GA_ST) * 4;
        const uint32_t sb = sBb + ((kt & 1) * GB_ST) * 4;
        #pragma unroll
        for (int kk = 0; kk < 4; kk++) {
            uint32_t a[2][4];
            #pragma unroll
            for (int mt = 0; mt < 2; mt++) {
                const int row = m0w + mt * 16 + (lane & 7) + ((lane >> 3) & 1) * 8;
                const int pr  = kk * 8 + ((lane >> 4) & 1) * 4;
                ldsm4(a[mt][0], a[mt][1], a[mt][2], a[mt][3],
                      sa + (row * GA_LD + pr) * 4);
            }
            #pragma unroll
            for (int ntp = 0; ntp < 4; ntp++) {
                uint32_t b0, b1, b2, b3;
                const uint32_t addr = sb +
                    ((kk * 16 + (lane & 7) + ((lane >> 3) & 1) * 8) * GB_LD +
                     (n0w >> 1) + ntp * 8 + ((lane >> 4) & 1) * 4) * 4;
                ldsm4t(b0, b1, b2, b3, addr);
                mma16(acc[0][2 * ntp],     a[0][0], a[0][1], a[0][2], a[0][3], b0, b1);
                mma16(acc[1][2 * ntp],     a[1][0], a[1][1], a[1][2], a[1][3], b0, b1);
                mma16(acc[0][2 * ntp + 1], a[0][0], a[0][1], a[0][2], a[0][3], b2, b3);
                mma16(acc[1][2 * ntp + 1], a[1][0], a[1][1], a[1][2], a[1][3], b2, b3);
            }
        }
    }

    #pragma unroll
    for (int mt = 0; mt < 2; mt++) {
        const int o0 = m0 + m0w + mt * 16 + g;
        const float bs0 = bias[o0], bs1 = bias[o0 + 8];
        #pragma unroll
        for (int nt = 0; nt < 8; nt++) {
            const int t = n0 + n0w + nt * 8 + 2 * tig;
            const size_t off0 = ((size_t)b * M + o0) * N + t;
            const size_t off1 = ((size_t)b * M + o0 + 8) * N + t;
            if (mode == 0) {
                __nv_bfloat16* Y = (__nv_bfloat16*)Yv;
                const float sc0 = (o0 < C_) ? 0.35355339059f * 1.44269504089f
                                 : ((o0 < 2 * C_) ? 0.35355339059f : 1.0f);
                const float sc1 = (o0 + 8 < C_) ? 0.35355339059f * 1.44269504089f
                                 : ((o0 + 8 < 2 * C_) ? 0.35355339059f : 1.0f);
                *(__nv_bfloat162*)&Y[off0] = __floats2bfloat162_rn(
                    (acc[mt][nt][0] + bs0) * sc0, (acc[mt][nt][1] + bs0) * sc0);
                *(__nv_bfloat162*)&Y[off1] = __floats2bfloat162_rn(
                    (acc[mt][nt][2] + bs1) * sc1, (acc[mt][nt][3] + bs1) * sc1);
            } else {
                float* Y = (float*)Yv;
                float2 r0 = *(const float2*)&resid[off0];
                float2 r1 = *(const float2*)&resid[off1];
                *(float2*)&Y[off0] = make_float2(acc[mt][nt][0] + bs0 + r0.x,
                                                 acc[mt][nt][1] + bs0 + r0.y);
                *(float2*)&Y[off1] = make_float2(acc[mt][nt][2] + bs1 + r1.x,
                                                 acc[mt][nt][3] + bs1 + r1.y);
            }
        }
    }
}

// ---------------------------------------------------------------------------
// Flash attention: ex2 interleaved into GEMM2; hoisted Q; register P;
// no-max softmax (log2-scaled q upstream).
// ---------------------------------------------------------------------------
#define AQ_LD 68
#define AK_LD 36
#define AQ_ST (64 * AQ_LD)
#define AK_ST (64 * AK_LD)
#define OFF_Q 0
#define OFF_K AQ_ST
#define OFF_V (OFF_K + 2 * AK_ST)
#define ATT_SMEM_U32 (OFF_V + 2 * AK_ST)
#define ATT_SMEM_BYTES (ATT_SMEM_U32 * 4)

__global__ __launch_bounds__(256, 2) void attn_kernel(
    const __nv_bfloat16* __restrict__ qkv, __nv_bfloat16* __restrict__ out) {
    extern __shared__ uint32_t smu[];
    const uint32_t smb = (uint32_t)__cvta_generic_to_shared(smu);
    const uint32_t Qb = smb + OFF_Q * 4;
    const uint32_t Kb = smb + OFF_K * 4;
    const uint32_t Vb = smb + OFF_V * 4;

    const int bh = blockIdx.y, b = bh >> 3, h = bh & 7;
    const int t0 = blockIdx.x * 128;
    const size_t headoff = ((size_t)b * 3 * C_ + h * CH) * T_;
    const __nv_bfloat16* qg = qkv + headoff;
    const __nv_bfloat16* kg = qkv + headoff + (size_t)C_ * T_;
    const __nv_bfloat16* vg = qkv + headoff + (size_t)2 * C_ * T_;

    const int tid = threadIdx.x;
    const int w = tid >> 5, lane = tid & 31;
    const int g = lane >> 2, tig = lane & 3;
    const int tA = w * 16 + g, tB = tA + 8;

    auto issueKV = [&](int it, int st) {
        const int s0 = it * 64;
        #pragma unroll
        for (int u = 0; u < 2; u++) {
            const int id = u * 256 + tid, r = id >> 3, ch = id & 7;
            cp16(Kb + (st * AK_ST + r * AK_LD + ch * 4) * 4,
                 &kg[(size_t)r * T_ + s0 + ch * 8]);
            cp16(Vb + (st * AK_ST + r * AK_LD + ch * 4) * 4,
                 &vg[(size_t)r * T_ + s0 + ch * 8]);
        }
        CP_COMMIT();
    };

    // prologue: Q (group 1), KV tile 0 (group 2)
    #pragma unroll
    for (int u = 0; u < 4; u++) {
        const int id = u * 256 + tid, r = id >> 4, ch = id & 15;
        cp16(Qb + (r * AQ_LD + ch * 4) * 4, &qg[(size_t)r * T_ + t0 + ch * 8]);
    }
    CP_COMMIT();
    issueKV(0, 0);
    CP_WAIT1();
    __syncthreads();

    uint32_t qf[4][4];
    #pragma unroll
    for (int kk = 0; kk < 4; kk++) {
        const int crA  = kk * 16 + ((lane >> 4) & 1) * 8 + (lane & 7);
        const int toff = w * 16 + ((lane >> 3) & 1) * 8;
        ldsm4t(qf[kk][0], qf[kk][1], qf[kk][2], qf[kk][3],
               Qb + crA * (AQ_LD * 4) + toff * 2);
    }

    float l0 = 0.f, l1 = 0.f;
    float O[8][4] = {};
    const int NT = T_ / 64;

    for (int it = 0; it < NT; it++) {
        CP_WAIT0();
        __syncthreads();
        if (it + 1 < NT) issueKV(it + 1, (it + 1) & 1);
        const uint32_t Kst = Kb + ((it & 1) * AK_ST) * 4;
        const uint32_t Vst = Vb + ((it & 1) * AK_ST) * 4;

        // ---- GEMM1 ----
        float S[8][4] = {};
        #pragma unroll
        for (int kk = 0; kk < 4; kk++) {
            #pragma unroll
            for (int ntp = 0; ntp < 4; ntp++) {
                uint32_t b0, b1, b2, b3;
                const uint32_t addr = Kst +
                    ((kk * 16 + (lane & 7) + ((lane >> 3) & 1) * 8) * AK_LD +
                     ntp * 8 + ((lane >> 4) & 1) * 4) * 4;
                ldsm4t(b0, b1, b2, b3, addr);
                mma16(S[2 * ntp],     qf[kk][0], qf[kk][1], qf[kk][2], qf[kk][3], b0, b1);
                mma16(S[2 * ntp + 1], qf[kk][0], qf[kk][1], qf[kk][2], qf[kk][3], b2, b3);
            }
        }

        // ---- GEMM2 with per-kk softmax (MUFU/HMMA interleave) ----
        #pragma unroll
        for (int kk = 0; kk < 4; kk++) {
            const float p00 = ex2(S[2 * kk][0]),     p01 = ex2(S[2 * kk][1]);
            const float p02 = ex2(S[2 * kk][2]),     p03 = ex2(S[2 * kk][3]);
            const float p10 = ex2(S[2 * kk + 1][0]), p11 = ex2(S[2 * kk + 1][1]);
            const float p12 = ex2(S[2 * kk + 1][2]), p13 = ex2(S[2 * kk + 1][3]);
            l0 += p00 + p01 + p10 + p11;
            l1 += p02 + p03 + p12 + p13;
            const uint32_t a0 = pack_bf16(p00, p01);
            const uint32_t a1 = pack_bf16(p02, p03);
            const uint32_t a2 = pack_bf16(p10, p11);
            const uint32_t a3 = pack_bf16(p12, p13);
            #pragma unroll
            for (int ntp = 0; ntp < 4; ntp++) {
                uint32_t b0, b1, b2, b3;
                const uint32_t addr = Vst +
                    ((ntp * 16 + (lane & 7) + ((lane >> 4) & 1) * 8) * AK_LD +
                     kk * 8 + ((lane >> 3) & 1) * 4) * 4;
                ldsm4(b0, b1, b2, b3, addr);
                mma16(O[2 * ntp],     a0, a1, a2, a3, b0, b1);
                mma16(O[2 * ntp + 1], a0, a1, a2, a3, b2, b3);
            }
        }
    }

    l0 += __shfl_xor_sync(0xffffffffu, l0, 1);
    l0 += __shfl_xor_sync(0xffffffffu, l0, 2);
    l1 += __shfl_xor_sync(0xffffffffu, l1, 1);
    l1 += __shfl_xor_sync(0xffffffffu, l1, 2);
    const float inv0 = 1.0f / l0, inv1 = 1.0f / l1;

    const size_t obase = ((size_t)b * C_ + h * CH) * T_;
    #pragma unroll
    for (int nt = 0; nt < 8; nt++) {
        const int c = nt * 8 + 2 * tig;
        out[obase + (size_t)c * T_ + t0 + tA]       = __float2bfloat16_rn(O[nt][0] * inv0);
        out[obase + (size_t)(c + 1) * T_ + t0 + tA] = __float2bfloat16_rn(O[nt][1] * inv0);
        out[obase + (size_t)c * T_ + t0 + tB]       = __float2bfloat16_rn(O[nt][2] * inv1);
        out[obase + (size_t)(c + 1) * T_ + t0 + tB] = __float2bfloat16_rn(O[nt][3] * inv1);
    }
}

// ---------------------------------------------------------------------------
extern "C" void kernel_launch(void* const* d_in, const int* in_sizes, int n_in,
                              void* d_out, int out_size) {
    (void)in_sizes; (void)n_in; (void)out_size;
    const float* x      = (const float*)d_in[0];
    const float* norm_w = (const float*)d_in[1];
    const float* norm_b = (const float*)d_in[2];
    const float* qkv_w  = (const float*)d_in[3];
    const float* qkv_b  = (const float*)d_in[4];
    const float* proj_w = (const float*)d_in[5];
    const float* proj_b = (const float*)d_in[6];
    float* out = (float*)d_out;

    __nv_bfloat16 *xn, *qkvp, *att, *wq, *wp;
    cudaGetSymbolAddress((void**)&xn,   g_xn);
    cudaGetSymbolAddress((void**)&qkvp, g_qkv);
    cudaGetSymbolAddress((void**)&att,  g_att);
    cudaGetSymbolAddress((void**)&wq,   g_wq);
    cudaGetSymbolAddress((void**)&wp,   g_wp);

    cudaFuncSetAttribute(attn_kernel, cudaFuncAttributeMaxDynamicSharedMemorySize,
                         ATT_SMEM_BYTES);
    cudaFuncSetAttribute(gemm_kernel, cudaFuncAttributeMaxDynamicSharedMemorySize,
                         GEMM_SMEM_BYTES);

    const int n1 = 3 * C_ * C_ / 4, n2 = C_ * C_ / 4;
    cvt2_kernel<<<(n1 + n2 + 255) / 256, 256>>>(qkv_w, wq, n1, proj_w, wp, n2);
    gn_kernel<<<B_ * NGROUPS, 1024>>>(x, norm_w, norm_b, xn);
    gemm_kernel<<<dim3(T_ / 128, 3 * C_ / 128, B_), 256, GEMM_SMEM_BYTES>>>(
        wq, xn, qkv_b, nullptr, qkvp, 3 * C_, 0);
    attn_kernel<<<dim3(T_ / 128, B_ * H_), 256, ATT_SMEM_BYTES>>>(qkvp, att);
    gemm_kernel<<<dim3(T_ / 128, C_ / 128, B_), 256, GEMM_SMEM_BYTES>>>(
        wp, att, proj_b, x, out, C_, 1);
}

// round 15
// speedup vs baseline: 1.0245x; 1.0245x over previous
#include <cuda_runtime.h>
#include <cuda_bf16.h>
#include <cstdint>

#define B_ 4
#define C_ 512
#define T_ 2048
#define H_ 8
#define CH 64
#define NGROUPS 32

// Scratch (static device arrays: allocation-free per harness rules)
__device__ __nv_bfloat16 g_xn [B_ * C_ * T_];
__device__ __nv_bfloat16 g_qkv[3 * B_ * C_ * T_];
__device__ __nv_bfloat16 g_att[B_ * C_ * T_];
__device__ __nv_bfloat16 g_wq [3 * C_ * C_];
__device__ __nv_bfloat16 g_wp [C_ * C_];

// ---------------------------------------------------------------------------
// helpers
// ---------------------------------------------------------------------------
__device__ __forceinline__ void mma16(float* d, uint32_t a0, uint32_t a1,
                                      uint32_t a2, uint32_t a3,
                                      uint32_t b0, uint32_t b1) {
    asm volatile(
        "mma.sync.aligned.m16n8k16.row.col.f32.bf16.bf16.f32 "
        "{%0,%1,%2,%3}, {%4,%5,%6,%7}, {%8,%9}, {%0,%1,%2,%3};\n"
        : "+f"(d[0]), "+f"(d[1]), "+f"(d[2]), "+f"(d[3])
        : "r"(a0), "r"(a1), "r"(a2), "r"(a3), "r"(b0), "r"(b1));
}
__device__ __forceinline__ void ldsm4(uint32_t& r0, uint32_t& r1, uint32_t& r2,
                                      uint32_t& r3, uint32_t addr) {
    asm volatile("ldmatrix.sync.aligned.m8n8.x4.shared.b16 {%0,%1,%2,%3}, [%4];"
                 : "=r"(r0), "=r"(r1), "=r"(r2), "=r"(r3) : "r"(addr));
}
__device__ __forceinline__ void ldsm4t(uint32_t& r0, uint32_t& r1, uint32_t& r2,
                                       uint32_t& r3, uint32_t addr) {
    asm volatile("ldmatrix.sync.aligned.m8n8.x4.trans.shared.b16 {%0,%1,%2,%3}, [%4];"
                 : "=r"(r0), "=r"(r1), "=r"(r2), "=r"(r3) : "r"(addr));
}
__device__ __forceinline__ void cp16(uint32_t dst, const void* src) {
    asm volatile("cp.async.cg.shared.global [%0], [%1], 16;\n" :: "r"(dst), "l"(src));
}
#define CP_COMMIT() asm volatile("cp.async.commit_group;\n" ::)
#define CP_WAIT0()  asm volatile("cp.async.wait_group 0;\n" ::)
#define CP_WAIT1()  asm volatile("cp.async.wait_group 1;\n" ::)

__device__ __forceinline__ uint32_t pack_bf16(float a, float b) {
    __nv_bfloat162 h = __floats2bfloat162_rn(a, b);
    return *(uint32_t*)&h;
}
__device__ __forceinline__ float ex2(float x) {
    float r;
    asm("ex2.approx.f32 %0, %1;" : "=f"(r) : "f"(x));
    return r;
}

// ---------------------------------------------------------------------------
// weights fp32 -> bf16 (both weight matrices in one launch)
// ---------------------------------------------------------------------------
__global__ __launch_bounds__(256) void cvt2_kernel(
    const float* __restrict__ s1, __nv_bfloat16* __restrict__ d1, int n1,
    const float* __restrict__ s2, __nv_bfloat16* __restrict__ d2, int n2) {
    const int i = blockIdx.x * 256 + threadIdx.x;
    const float* src; __nv_bfloat16* dst; int j;
    if (i < n1) { src = s1; dst = d1; j = i; }
    else if (i < n1 + n2) { src = s2; dst = d2; j = i - n1; }
    else return;
    float4 v = ((const float4*)src)[j];
    ((__nv_bfloat162*)dst)[2 * j]     = __floats2bfloat162_rn(v.x, v.y);
    ((__nv_bfloat162*)dst)[2 * j + 1] = __floats2bfloat162_rn(v.z, v.w);
}

// ---------------------------------------------------------------------------
// GroupNorm (fp32 in, bf16 out), 1024 threads
// ---------------------------------------------------------------------------
__global__ __launch_bounds__(1024) void gn_kernel(const float* __restrict__ x,
                                                  const float* __restrict__ w,
                                                  const float* __restrict__ bb,
                                                  __nv_bfloat16* __restrict__ out) {
    const int blk = blockIdx.x;
    const int g = blk & (NGROUPS - 1);
    const size_t base = (size_t)blk * (16 * T_);
    const float* xp = x + base;
    __nv_bfloat162* op = (__nv_bfloat162*)(out + base);
    const int tid = threadIdx.x;

    float s = 0.f, sq = 0.f;
    #pragma unroll
    for (int u = 0; u < 8; u++) {
        float4 v = ((const float4*)xp)[u * 1024 + tid];
        s  += v.x + v.y + v.z + v.w;
        sq += v.x * v.x + v.y * v.y + v.z * v.z + v.w * v.w;
    }
    #pragma unroll
    for (int o = 16; o; o >>= 1) {
        s  += __shfl_xor_sync(0xffffffffu, s,  o);
        sq += __shfl_xor_sync(0xffffffffu, sq, o);
    }
    __shared__ float rs[32], rq[32];
    __shared__ float mean_s, inv_s;
    const int warp = tid >> 5, lane = tid & 31;
    if (lane == 0) { rs[warp] = s; rq[warp] = sq; }
    __syncthreads();
    if (tid == 0) {
        float ts = 0.f, tq = 0.f;
        #pragma unroll
        for (int i = 0; i < 32; i++) { ts += rs[i]; tq += rq[i]; }
        const float inv_n = 1.0f / (16.0f * T_);
        float mean = ts * inv_n;
        float var = tq * inv_n - mean * mean;
        mean_s = mean;
        inv_s = rsqrtf(var + 1e-5f);
    }
    __syncthreads();
    const float mean = mean_s, inv = inv_s;
    #pragma unroll
    for (int u = 0; u < 8; u++) {
        const int i = u * 1024 + tid;
        const int c = (g << 4) + (i >> 9);
        const float wc = w[c], bc = bb[c];
        float4 v = ((const float4*)xp)[i];
        v.x = (v.x - mean) * inv * wc + bc;
        v.y = (v.y - mean) * inv * wc + bc;
        v.z = (v.z - mean) * inv * wc + bc;
        v.w = (v.w - mean) * inv * wc + bc;
        op[2 * i]     = __floats2bfloat162_rn(v.x, v.y);
        op[2 * i + 1] = __floats2bfloat162_rn(v.z, v.w);
    }
}

// ---------------------------------------------------------------------------
// bf16 tensor-core GEMM: block 128x128, k-tile 64, batched fragment loads.
// mode 0: bf16 out w/ q,k scaling; mode 1: fp32 + resid.
// ---------------------------------------------------------------------------
#define GA_LD 36
#define GB_LD 68
#define GA_ST (128 * GA_LD)
#define GB_ST (64 * GB_LD)
#define GEMM_SMEM_BYTES ((2 * GA_ST + 2 * GB_ST) * 4)

__global__ __launch_bounds__(256, 2) void gemm_kernel(
    const __nv_bfloat16* __restrict__ W, const __nv_bfloat16* __restrict__ X,
    const float* __restrict__ bias, const float* __restrict__ resid,
    void* __restrict__ Yv, int M, int mode) {
    const int N = T_, K = C_;
    extern __shared__ uint32_t smg[];
    const uint32_t sAb = (uint32_t)__cvta_generic_to_shared(smg);
    const uint32_t sBb = sAb + 2 * GA_ST * 4;

    const int n0 = blockIdx.x * 128, m0 = blockIdx.y * 128, b = blockIdx.z;
    const __nv_bfloat16* Xb = X + (size_t)b * K * N;
    const int tid = threadIdx.x;
    const int w = tid >> 5, lane = tid & 31;
    const int g = lane >> 2, tig = lane & 3;
    const int m0w = (w & 3) * 32, n0w = (w >> 2) * 64;

    auto issue = [&](int kt, int st) {
        const int k0 = kt * 64;
        #pragma unroll
        for (int u = 0; u < 4; u++) {
            const int id = u * 256 + tid, r = id >> 3, ch = id & 7;
            cp16(sAb + (st * GA_ST + r * GA_LD + ch * 4) * 4,
                 &W[(size_t)(m0 + r) * K + k0 + ch * 8]);
        }
        #pragma unroll
        for (int u = 0; u < 4; u++) {
            const int id = u * 256 + tid, r = id >> 4, ch = id & 15;
            cp16(sBb + (st * GB_ST + r * GB_LD + ch * 4) * 4,
                 &Xb[(size_t)(k0 + r) * N + n0 + ch * 8]);
        }
        CP_COMMIT();
    };

    float acc[2][8][4] = {};
    issue(0, 0);
    const int NT = K / 64;
    for (int kt = 0; kt < NT; kt++) {
        CP_WAIT0();
        __syncthreads();
        if (kt + 1 < NT) issue(kt + 1, (kt + 1) & 1);
        const uint32_t sa = sAb + ((kt & 1) * GA_ST) * 4;
        const uint32_t sb = sBb + ((kt & 1) * GB_ST) * 4;
        #pragma unroll
        for (int kk = 0; kk < 4; kk++) {
            uint32_t a[2][4], bf[4][4];
            #pragma unroll
            for (int mt = 0; mt < 2; mt++) {
                const int row = m0w + mt * 16 + (lane & 7) + ((lane >> 3) & 1) * 8;
                const int pr  = kk * 8 + ((lane >> 4) & 1) * 4;
                ldsm4(a[mt][0], a[mt][1], a[mt][2], a[mt][3],
                      sa + (row * GA_LD + pr) * 4);
            }
            #pragma unroll
            for (int ntp = 0; ntp < 4; ntp++) {
                const uint32_t addr = sb +
                    ((kk * 16 + (lane & 7) + ((lane >> 3) & 1) * 8) * GB_LD +
                     (n0w >> 1) + ntp * 8 + ((lane >> 4) & 1) * 4) * 4;
                ldsm4t(bf[ntp][0], bf[ntp][1], bf[ntp][2], bf[ntp][3], addr);
            }
            #pragma unroll
            for (int ntp = 0; ntp < 4; ntp++) {
                mma16(acc[0][2 * ntp],     a[0][0], a[0][1], a[0][2], a[0][3], bf[ntp][0], bf[ntp][1]);
                mma16(acc[1][2 * ntp],     a[1][0], a[1][1], a[1][2], a[1][3], bf[ntp][0], bf[ntp][1]);
                mma16(acc[0][2 * ntp + 1], a[0][0], a[0][1], a[0][2], a[0][3], bf[ntp][2], bf[ntp][3]);
                mma16(acc[1][2 * ntp + 1], a[1][0], a[1][1], a[1][2], a[1][3], bf[ntp][2], bf[ntp][3]);
            }
        }
    }

    #pragma unroll
    for (int mt = 0; mt < 2; mt++) {
        const int o0 = m0 + m0w + mt * 16 + g;
        const float bs0 = bias[o0], bs1 = bias[o0 + 8];
        #pragma unroll
        for (int nt = 0; nt < 8; nt++) {
            const int t = n0 + n0w + nt * 8 + 2 * tig;
            const size_t off0 = ((size_t)b * M + o0) * N + t;
            const size_t off1 = ((size_t)b * M + o0 + 8) * N + t;
            if (mode == 0) {
                __nv_bfloat16* Y = (__nv_bfloat16*)Yv;
                const float sc0 = (o0 < C_) ? 0.35355339059f * 1.44269504089f
                                 : ((o0 < 2 * C_) ? 0.35355339059f : 1.0f);
                const float sc1 = (o0 + 8 < C_) ? 0.35355339059f * 1.44269504089f
                                 : ((o0 + 8 < 2 * C_) ? 0.35355339059f : 1.0f);
                *(__nv_bfloat162*)&Y[off0] = __floats2bfloat162_rn(
                    (acc[mt][nt][0] + bs0) * sc0, (acc[mt][nt][1] + bs0) * sc0);
                *(__nv_bfloat162*)&Y[off1] = __floats2bfloat162_rn(
                    (acc[mt][nt][2] + bs1) * sc1, (acc[mt][nt][3] + bs1) * sc1);
            } else {
                float* Y = (float*)Yv;
                float2 r0 = *(const float2*)&resid[off0];
                float2 r1 = *(const float2*)&resid[off1];
                *(float2*)&Y[off0] = make_float2(acc[mt][nt][0] + bs0 + r0.x,
                                                 acc[mt][nt][1] + bs0 + r0.y);
                *(float2*)&Y[off1] = make_float2(acc[mt][nt][2] + bs1 + r1.x,
                                                 acc[mt][nt][3] + bs1 + r1.y);
            }
        }
    }
}

// ---------------------------------------------------------------------------
// Flash attention: batched fragment loads per kk; separate ex2 phase;
// hoisted Q; register P; no-max softmax (log2-scaled q upstream).
// ---------------------------------------------------------------------------
#define AQ_LD 68
#define AK_LD 36
#define AQ_ST (64 * AQ_LD)
#define AK_ST (64 * AK_LD)
#define OFF_Q 0
#define OFF_K AQ_ST
#define OFF_V (OFF_K + 2 * AK_ST)
#define ATT_SMEM_U32 (OFF_V + 2 * AK_ST)
#define ATT_SMEM_BYTES (ATT_SMEM_U32 * 4)

__global__ __launch_bounds__(256, 2) void attn_kernel(
    const __nv_bfloat16* __restrict__ qkv, __nv_bfloat16* __restrict__ out) {
    extern __shared__ uint32_t smu[];
    const uint32_t smb = (uint32_t)__cvta_generic_to_shared(smu);
    const uint32_t Qb = smb + OFF_Q * 4;
    const uint32_t Kb = smb + OFF_K * 4;
    const uint32_t Vb = smb + OFF_V * 4;

    const int bh = blockIdx.y, b = bh >> 3, h = bh & 7;
    const int t0 = blockIdx.x * 128;
    const size_t headoff = ((size_t)b * 3 * C_ + h * CH) * T_;
    const __nv_bfloat16* qg = qkv + headoff;
    const __nv_bfloat16* kg = qkv + headoff + (size_t)C_ * T_;
    const __nv_bfloat16* vg = qkv + headoff + (size_t)2 * C_ * T_;

    const int tid = threadIdx.x;
    const int w = tid >> 5, lane = tid & 31;
    const int g = lane >> 2, tig = lane & 3;
    const int tA = w * 16 + g, tB = tA + 8;

    auto issueKV = [&](int it, int st) {
        const int s0 = it * 64;
        #pragma unroll
        for (int u = 0; u < 2; u++) {
            const int id = u * 256 + tid, r = id >> 3, ch = id & 7;
            cp16(Kb + (st * AK_ST + r * AK_LD + ch * 4) * 4,
                 &kg[(size_t)r * T_ + s0 + ch * 8]);
            cp16(Vb + (st * AK_ST + r * AK_LD + ch * 4) * 4,
                 &vg[(size_t)r * T_ + s0 + ch * 8]);
        }
        CP_COMMIT();
    };

    // prologue: Q (group 1), KV tile 0 (group 2)
    #pragma unroll
    for (int u = 0; u < 4; u++) {
        const int id = u * 256 + tid, r = id >> 4, ch = id & 15;
        cp16(Qb + (r * AQ_LD + ch * 4) * 4, &qg[(size_t)r * T_ + t0 + ch * 8]);
    }
    CP_COMMIT();
    issueKV(0, 0);
    CP_WAIT1();
    __syncthreads();

    uint32_t qf[4][4];
    #pragma unroll
    for (int kk = 0; kk < 4; kk++) {
        const int crA  = kk * 16 + ((lane >> 4) & 1) * 8 + (lane & 7);
        const int toff = w * 16 + ((lane >> 3) & 1) * 8;
        ldsm4t(qf[kk][0], qf[kk][1], qf[kk][2], qf[kk][3],
               Qb + crA * (AQ_LD * 4) + toff * 2);
    }

    float l0 = 0.f, l1 = 0.f;
    float O[8][4] = {};
    const int NT = T_ / 64;

    for (int it = 0; it < NT; it++) {
        CP_WAIT0();
        __syncthreads();
        if (it + 1 < NT) issueKV(it + 1, (it + 1) & 1);
        const uint32_t Kst = Kb + ((it & 1) * AK_ST) * 4;
        const uint32_t Vst = Vb + ((it & 1) * AK_ST) * 4;

        // ---- GEMM1: batched K fragment loads per kk ----
        float S[8][4] = {};
        #pragma unroll
        for (int kk = 0; kk < 4; kk++) {
            uint32_t bf[4][4];
            #pragma unroll
            for (int ntp = 0; ntp < 4; ntp++) {
                const uint32_t addr = Kst +
                    ((kk * 16 + (lane & 7) + ((lane >> 3) & 1) * 8) * AK_LD +
                     ntp * 8 + ((lane >> 4) & 1) * 4) * 4;
                ldsm4t(bf[ntp][0], bf[ntp][1], bf[ntp][2], bf[ntp][3], addr);
            }
            #pragma unroll
            for (int ntp = 0; ntp < 4; ntp++) {
                mma16(S[2 * ntp],     qf[kk][0], qf[kk][1], qf[kk][2], qf[kk][3],
                      bf[ntp][0], bf[ntp][1]);
                mma16(S[2 * ntp + 1], qf[kk][0], qf[kk][1], qf[kk][2], qf[kk][3],
                      bf[ntp][2], bf[ntp][3]);
            }
        }

        // ---- softmax numerators (separate phase) ----
        uint32_t pa[8], pb[8];
        #pragma unroll
        for (int nt = 0; nt < 8; nt++) {
            const float p0 = ex2(S[nt][0]);
            const float p1 = ex2(S[nt][1]);
            const float p2 = ex2(S[nt][2]);
            const float p3 = ex2(S[nt][3]);
            l0 += p0 + p1;
            l1 += p2 + p3;
            pa[nt] = pack_bf16(p0, p1);
            pb[nt] = pack_bf16(p2, p3);
        }

        // ---- GEMM2: batched V fragment loads per kk ----
        #pragma unroll
        for (int kk = 0; kk < 4; kk++) {
            uint32_t bf[4][4];
            #pragma unroll
            for (int ntp = 0; ntp < 4; ntp++) {
                const uint32_t addr = Vst +
                    ((ntp * 16 + (lane & 7) + ((lane >> 4) & 1) * 8) * AK_LD +
                     kk * 8 + ((lane >> 3) & 1) * 4) * 4;
                ldsm4(bf[ntp][0], bf[ntp][1], bf[ntp][2], bf[ntp][3], addr);
            }
            const uint32_t a0 = pa[2 * kk], a1 = pb[2 * kk];
            const uint32_t a2 = pa[2 * kk + 1], a3 = pb[2 * kk + 1];
            #pragma unroll
            for (int ntp = 0; ntp < 4; ntp++) {
                mma16(O[2 * ntp],     a0, a1, a2, a3, bf[ntp][0], bf[ntp][1]);
                mma16(O[2 * ntp + 1], a0, a1, a2, a3, bf[ntp][2], bf[ntp][3]);
            }
        }
    }

    l0 += __shfl_xor_sync(0xffffffffu, l0, 1);
    l0 += __shfl_xor_sync(0xffffffffu, l0, 2);
    l1 += __shfl_xor_sync(0xffffffffu, l1, 1);
    l1 += __shfl_xor_sync(0xffffffffu, l1, 2);
    const float inv0 = 1.0f / l0, inv1 = 1.0f / l1;

    const size_t obase = ((size_t)b * C_ + h * CH) * T_;
    #pragma unroll
    for (int nt = 0; nt < 8; nt++) {
        const int c = nt * 8 + 2 * tig;
        out[obase + (size_t)c * T_ + t0 + tA]       = __float2bfloat16_rn(O[nt][0] * inv0);
        out[obase + (size_t)(c + 1) * T_ + t0 + tA] = __float2bfloat16_rn(O[nt][1] * inv0);
        out[obase + (size_t)c * T_ + t0 + tB]       = __float2bfloat16_rn(O[nt][2] * inv1);
        out[obase + (size_t)(c + 1) * T_ + t0 + tB] = __float2bfloat16_rn(O[nt][3] * inv1);
    }
}

// ---------------------------------------------------------------------------
extern "C" void kernel_launch(void* const* d_in, const int* in_sizes, int n_in,
                              void* d_out, int out_size) {
    (void)in_sizes; (void)n_in; (void)out_size;
    const float* x      = (const float*)d_in[0];
    const float* norm_w = (const float*)d_in[1];
    const float* norm_b = (const float*)d_in[2];
    const float* qkv_w  = (const float*)d_in[3];
    const float* qkv_b  = (const float*)d_in[4];
    const float* proj_w = (const float*)d_in[5];
    const float* proj_b = (const float*)d_in[6];
    float* out = (float*)d_out;

    __nv_bfloat16 *xn, *qkvp, *att, *wq, *wp;
    cudaGetSymbolAddress((void**)&xn,   g_xn);
    cudaGetSymbolAddress((void**)&qkvp, g_qkv);
    cudaGetSymbolAddress((void**)&att,  g_att);
    cudaGetSymbolAddress((void**)&wq,   g_wq);
    cudaGetSymbolAddress((void**)&wp,   g_wp);

    cudaFuncSetAttribute(attn_kernel, cudaFuncAttributeMaxDynamicSharedMemorySize,
                         ATT_SMEM_BYTES);
    cudaFuncSetAttribute(gemm_kernel, cudaFuncAttributeMaxDynamicSharedMemorySize,
                         GEMM_SMEM_BYTES);

    const int n1 = 3 * C_ * C_ / 4, n2 = C_ * C_ / 4;
    cvt2_kernel<<<(n1 + n2 + 255) / 256, 256>>>(qkv_w, wq, n1, proj_w, wp, n2);
    gn_kernel<<<B_ * NGROUPS, 1024>>>(x, norm_w, norm_b, xn);
    gemm_kernel<<<dim3(T_ / 128, 3 * C_ / 128, B_), 256, GEMM_SMEM_BYTES>>>(
        wq, xn, qkv_b, nullptr, qkvp, 3 * C_, 0);
    attn_kernel<<<dim3(T_ / 128, B_ * H_), 256, ATT_SMEM_BYTES>>>(qkvp, att);
    gemm_kernel<<<dim3(T_ / 128, C_ / 128, B_), 256, GEMM_SMEM_BYTES>>>(
        wp, att, proj_b, x, out, C_, 1);
}